// round 7
// baseline (speedup 1.0000x reference)
#include <cuda_runtime.h>
#include <cuda_bf16.h>
#include <cstdint>

#define NN 50000
#define NG 64
#define MAXE 800000
#define MAXH 512
#define BN_EPS 1e-5f
#define SCAN_B 1024

// ================= scratch (device globals) ===================================
__device__ __align__(16) float g_h[(size_t)NN * MAXH];
__device__ __align__(16) float g_agg[(size_t)NN * MAXH];
__device__ __align__(16) __nv_bfloat16 g_ahi[(size_t)NN * MAXH];
__device__ __align__(16) __nv_bfloat16 g_alo[(size_t)NN * MAXH];
__device__ __align__(16) __nv_bfloat16 g_wthi[MAXH * MAXH];
__device__ __align__(16) __nv_bfloat16 g_wtlo[MAXH * MAXH];
__device__ float g_dinv[NN];
__device__ int   g_cnt[NN];
__device__ int   g_cursor[NN];
__device__ int   g_off[NN + 1];
__device__ int   g_bsum[64];
__device__ int   g_csrc[MAXE];
__device__ float g_cw[MAXE];
__device__ double g_sumd[MAXH];
__device__ double g_sqsd[MAXH];
__device__ __align__(16) float g_mean[MAXH];
__device__ __align__(16) float g_scale[MAXH];
__device__ int   g_gstart[NG + 1];

// ================= CSR build ===================================================
__global__ void k_zeroi(int* p, int n) {
    int i = blockIdx.x * blockDim.x + threadIdx.x;
    if (i < n) p[i] = 0;
}
__global__ void k_count(const int* __restrict__ col, int* cnt, int E) {
    int i = blockIdx.x * blockDim.x + threadIdx.x;
    if (i < E) atomicAdd(&cnt[col[i]], 1);
}
__global__ void k_scan1(const int* __restrict__ cnt, int* off, int* bsum, int n) {
    __shared__ int sh[SCAN_B];
    int i = blockIdx.x * SCAN_B + threadIdx.x;
    sh[threadIdx.x] = (i < n) ? cnt[i] : 0;
    __syncthreads();
#pragma unroll
    for (int d = 1; d < SCAN_B; d <<= 1) {
        int t = (threadIdx.x >= d) ? sh[threadIdx.x - d] : 0;
        __syncthreads();
        sh[threadIdx.x] += t;
        __syncthreads();
    }
    if (i < n) off[i + 1] = sh[threadIdx.x];
    if (threadIdx.x == SCAN_B - 1) bsum[blockIdx.x] = sh[SCAN_B - 1];
}
__global__ void k_scan2(int* bsum, int nb, int* off) {
    if (threadIdx.x == 0) {
        off[0] = 0;
        int s = 0;
        for (int b = 0; b < nb; b++) { s += bsum[b]; bsum[b] = s; }
    }
}
__global__ void k_scan3(int* off, const int* __restrict__ bsum, int n) {
    int b = blockIdx.x + 1;
    int i = b * SCAN_B + threadIdx.x;
    if (i < n) off[i + 1] += bsum[b - 1];
}
__global__ void k_dinv2(const int* __restrict__ cnt, float* dinv, int n) {
    int i = blockIdx.x * blockDim.x + threadIdx.x;
    if (i < n) dinv[i] = rsqrtf((float)(cnt[i] + 1));
}
__global__ void k_place(const int* __restrict__ row, const int* __restrict__ col,
                        const float* __restrict__ dinv, const int* __restrict__ off,
                        int* cursor, int* csrc, float* cw, int E) {
    int e = blockIdx.x * blockDim.x + threadIdx.x;
    if (e >= E) return;
    int d = col[e], r = row[e];
    int pos = off[d] + atomicAdd(&cursor[d], 1);
    csrc[pos] = r;
    cw[pos] = dinv[r] * dinv[d];
}

// ================= bf16 split kernels ==========================================
__global__ void k_split_plain(const float* __restrict__ src, __nv_bfloat16* hi,
                              __nv_bfloat16* lo, int total) {
    int i = blockIdx.x * blockDim.x + threadIdx.x;
    if (i >= total) return;
    float v = src[i];
    __nv_bfloat16 h = __float2bfloat16(v);
    hi[i] = h;
    lo[i] = __float2bfloat16(v - __bfloat162float(h));
}
__global__ void k_split_bn(const float* __restrict__ src, __nv_bfloat16* hi,
                           __nv_bfloat16* lo, const float* __restrict__ mean,
                           const float* __restrict__ scale, const float* __restrict__ be,
                           int total, int kmask) {
    int i = blockIdx.x * blockDim.x + threadIdx.x;
    if (i >= total) return;
    int c = i & kmask;
    float v = fmaxf((src[i] - mean[c]) * scale[c] + be[c], 0.f);
    __nv_bfloat16 h = __float2bfloat16(v);
    hi[i] = h;
    lo[i] = __float2bfloat16(v - __bfloat162float(h));
}
// transpose + split: Wt[n*K+k] = W[k*N+n]
__global__ void k_split_wt(const float* __restrict__ W, __nv_bfloat16* hi,
                           __nv_bfloat16* lo, int K, int N) {
    int i = blockIdx.x * blockDim.x + threadIdx.x;
    if (i >= K * N) return;
    int n = i / K, k = i - n * K;
    float v = W[(size_t)k * N + n];
    __nv_bfloat16 h = __float2bfloat16(v);
    hi[i] = h;
    lo[i] = __float2bfloat16(v - __bfloat162float(h));
}

// ================= mma.sync bf16 split GEMM ====================================
// C[M,N] = A@W (A row-major [M,K], Wt row-major [N,K]); K_eff = 3K phases:
//   phase0: Ahi*Bhi, phase1: Alo*Bhi, phase2: Ahi*Blo
// CTA tile 128x128; 8 warps, warp tile 64x32. KC=64 per chunk.
// Epilogue: H = C ; AGG = C*dinv[row]^2 + bias[col]
#define KC 64
#define TSTR 72                         // bf16 elems per tile row (144B, conflict-free)
#define TILE_E (128 * TSTR)
#define SMEM_GEMM (2 * 2 * TILE_E * 2)  // 73728 B

__device__ __forceinline__ uint32_t smem_u32(const void* p) {
    uint32_t a;
    asm("{ .reg .u64 t; cvta.to.shared.u64 t, %1; cvt.u32.u64 %0, t; }"
        : "=r"(a) : "l"(p));
    return a;
}
__device__ __forceinline__ void ldsm_x4(uint32_t* r, uint32_t addr) {
    asm volatile("ldmatrix.sync.aligned.m8n8.x4.shared.b16 {%0,%1,%2,%3}, [%4];"
                 : "=r"(r[0]), "=r"(r[1]), "=r"(r[2]), "=r"(r[3]) : "r"(addr));
}
__device__ __forceinline__ void mma16816(float* c, const uint32_t* a, const uint32_t* b) {
    asm volatile(
        "mma.sync.aligned.m16n8k16.row.col.f32.bf16.bf16.f32 "
        "{%0,%1,%2,%3}, {%4,%5,%6,%7}, {%8,%9}, {%0,%1,%2,%3};"
        : "+f"(c[0]), "+f"(c[1]), "+f"(c[2]), "+f"(c[3])
        : "r"(a[0]), "r"(a[1]), "r"(a[2]), "r"(a[3]), "r"(b[0]), "r"(b[1]));
}

// load one 128xKC bf16 tile via float4 (4 iterations)
__device__ __forceinline__ void load_tile(char* sm, int tb,
                                          const __nv_bfloat16* __restrict__ src,
                                          int rowBase, int Mlim, int K, int k0, int tid) {
#pragma unroll
    for (int it = 0; it < 4; it++) {
        int q = it * 256 + tid;
        int r = q >> 3;                  // 0..127
        int kc = (q & 7) << 3;           // bf16 col, step 8 (16B)
        float4 v = make_float4(0.f, 0.f, 0.f, 0.f);
        int grow = rowBase + r;
        if (grow < Mlim)
            v = *(const float4*)(src + (size_t)grow * K + k0 + kc);
        *(float4*)(sm + tb + (r * TSTR + kc) * 2) = v;
    }
}

__global__ __launch_bounds__(256, 1)
void k_mma_gemm(const __nv_bfloat16* __restrict__ Ahi, const __nv_bfloat16* __restrict__ Alo,
                const __nv_bfloat16* __restrict__ Bhi, const __nv_bfloat16* __restrict__ Blo,
                float* __restrict__ Hout, float* __restrict__ AGG,
                const float* __restrict__ dinv, const float* __restrict__ bias,
                int M, int K, int N) {
    extern __shared__ char sm[];
    const uint32_t sb = smem_u32(sm);
    const int tid = threadIdx.x;
    const int wid = tid >> 5;
    const int lane = tid & 31;
    const int rowBase = blockIdx.y * 128;
    const int colBase = blockIdx.x * 128;

    const int warp_m = wid & 1;          // 2 x 64 rows
    const int warp_n = wid >> 1;         // 4 x 32 cols

    const int bufA[2] = {0, 4 * TILE_E};
    const int bufB[2] = {2 * TILE_E, 6 * TILE_E};

    const int nk = K / KC;
    const int NC = 3 * nk;

    float acc[4][4][4] = {};             // [mf][nf][reg]

    auto srcA = [&](int phase) { return (phase == 1) ? Alo : Ahi; };
    auto srcB = [&](int phase) { return (phase == 2) ? Blo : Bhi; };

    load_tile(sm, bufA[0], Ahi, rowBase, M, K, 0, tid);
    load_tile(sm, bufB[0], Bhi, colBase, N, K, 0, tid);
    __syncthreads();

    // A ldmatrix lane addressing
    const int a_row = warp_m * 64 + (lane & 7) + ((lane >> 3) & 1) * 8;  // + mf*16
    const int a_col = ((lane >> 4) & 1) * 8;                              // + ks*16
    // B ldmatrix x4 lane addressing: covers 2 nf (16 rows) x 16 cols
    const int bg = lane >> 3;                                             // 0..3
    const int b_row = warp_n * 32 + (bg >> 1) * 8 + (lane & 7);           // + npair*16
    const int b_col = (bg & 1) * 8;                                       // + ks*16

    for (int c = 0; c < NC; c++) {
        int b = c & 1;
        if (c + 1 < NC) {
            int cn = c + 1;
            int phase = cn / nk;
            int k0 = (cn - phase * nk) * KC;
            load_tile(sm, bufA[b ^ 1], srcA(phase), rowBase, M, K, k0, tid);
            load_tile(sm, bufB[b ^ 1], srcB(phase), colBase, N, K, k0, tid);
        }

        uint32_t Abase = sb + bufA[b];
        uint32_t Bbase = sb + bufB[b];
#pragma unroll
        for (int ks = 0; ks < 4; ks++) {
            uint32_t afr[4][4], bfr[2][4];
#pragma unroll
            for (int mf = 0; mf < 4; mf++)
                ldsm_x4(afr[mf],
                        Abase + (((a_row + mf * 16) * TSTR) + a_col + ks * 16) * 2);
#pragma unroll
            for (int np = 0; np < 2; np++)
                ldsm_x4(bfr[np],
                        Bbase + (((b_row + np * 16) * TSTR) + b_col + ks * 16) * 2);
#pragma unroll
            for (int mf = 0; mf < 4; mf++)
#pragma unroll
                for (int nf = 0; nf < 4; nf++)
                    mma16816(acc[mf][nf], afr[mf], &bfr[nf >> 1][(nf & 1) * 2]);
        }
        __syncthreads();
    }

    // epilogue
    const int gid = lane >> 2;
    const int tg = lane & 3;
#pragma unroll
    for (int mf = 0; mf < 4; mf++) {
#pragma unroll
        for (int half = 0; half < 2; half++) {
            int gr = rowBase + warp_m * 64 + mf * 16 + gid + half * 8;
            if (gr >= M) continue;
            float di = dinv[gr];
            float d2 = di * di;
            size_t base = (size_t)gr * N;
#pragma unroll
            for (int nf = 0; nf < 4; nf++) {
                int gc = colBase + warp_n * 32 + nf * 8 + tg * 2;
                float c0 = acc[mf][nf][half * 2 + 0];
                float c1 = acc[mf][nf][half * 2 + 1];
                *(float2*)&Hout[base + gc] = make_float2(c0, c1);
                float b0 = bias[gc], b1 = bias[gc + 1];
                *(float2*)&AGG[base + gc] =
                    make_float2(c0 * d2 + b0, c1 * d2 + b1);
            }
        }
    }
}

// ================= CSR gather ===================================================
__global__ void k_gather(const float* __restrict__ h, const int* __restrict__ csrc,
                         const float* __restrict__ cw, const int* __restrict__ off,
                         float* __restrict__ agg, int H, int tpnshift) {
    int tpn = 1 << tpnshift;
    int local = threadIdx.x >> tpnshift;
    int node = blockIdx.x * (blockDim.x >> tpnshift) + local;
    if (node >= NN) return;
    int c = (threadIdx.x & (tpn - 1)) << 2;
    int s = __ldg(&off[node]);
    int e = __ldg(&off[node + 1]);
    float ax = 0.f, ay = 0.f, az = 0.f, aw = 0.f;
    for (int i = s; i < e; i++) {
        int src = __ldg(&csrc[i]);
        float w = __ldg(&cw[i]);
        float4 v = __ldg((const float4*)(h + (size_t)src * H + c));
        ax += v.x * w; ay += v.y * w; az += v.z * w; aw += v.w * w;
    }
    float4 cur = *(float4*)&agg[(size_t)node * H + c];
    cur.x += ax; cur.y += ay; cur.z += az; cur.w += aw;
    *(float4*)&agg[(size_t)node * H + c] = cur;
}

// ================= BN statistics (fp64 accumulate) ==============================
__global__ void k_zerod(double* a, double* b, int n) {
    int i = blockIdx.x * blockDim.x + threadIdx.x;
    if (i < n) { a[i] = 0.0; b[i] = 0.0; }
}
__global__ void k_stats(const float* __restrict__ x, int rows, int H,
                        double* __restrict__ sum, double* __restrict__ sqs) {
    int c = blockIdx.x * blockDim.x + threadIdx.x;
    if (c >= H) return;
    double s = 0.0, q = 0.0;
    for (int r = blockIdx.y; r < rows; r += gridDim.y) {
        double v = (double)x[(size_t)r * H + c];
        s += v;
        q += v * v;
    }
    atomicAdd(&sum[c], s);
    atomicAdd(&sqs[c], q);
}
__global__ void k_bnparam(const double* __restrict__ sum, const double* __restrict__ sqs,
                          const float* __restrict__ g, float* __restrict__ mean,
                          float* __restrict__ scale, int H) {
    int c = blockIdx.x * blockDim.x + threadIdx.x;
    if (c >= H) return;
    const double invN = 1.0 / (double)NN;
    double m = sum[c] * invN;
    double var = sqs[c] * invN - m * m;
    mean[c] = (float)m;
    scale[c] = g[c] * (float)rsqrt(var + (double)BN_EPS);
}

// ================= graph boundaries + pool head =================================
__global__ void k_bounds(const int* __restrict__ batch, int* gstart, int n) {
    int i = blockIdx.x * blockDim.x + threadIdx.x;
    if (i >= n) return;
    int bi = batch[i];
    int bp = (i == 0) ? -1 : batch[i - 1];
    for (int g = bp + 1; g <= bi; g++) gstart[g] = i;
    if (i == n - 1)
        for (int g = bi + 1; g <= NG; g++) gstart[g] = n;
}
__global__ void k_pool_head(const float* __restrict__ agg, const int* __restrict__ gstart,
                            const float* __restrict__ mean, const float* __restrict__ scale,
                            const float* __restrict__ be, const float* __restrict__ Wo,
                            const float* __restrict__ bo, float* __restrict__ out) {
    __shared__ float pooled[128];
    int g = blockIdx.x;
    int c = threadIdx.x;
    int s = gstart[g], e = gstart[g + 1];
    float mn = mean[c], sc = scale[c], bb = be[c];
    float acc = 0.f;
    for (int n = s; n < e; n++)
        acc += fmaxf((agg[(size_t)n * 128 + c] - mn) * sc + bb, 0.f);
    float inv = 1.0f / (float)max(e - s, 1);
    pooled[c] = acc * inv;
    __syncthreads();
    if (c < 10) {
        float o = bo[c];
#pragma unroll 8
        for (int k = 0; k < 128; k++)
            o += pooled[k] * Wo[k * 10 + c];
        out[g * 10 + c] = o;
    }
}

// ================= host orchestration ===========================================
static inline int ilog2(int v) { int s = 0; while ((1 << s) < v) s++; return s; }

struct Ptrs {
    float *h, *agg, *dinv, *mean, *scale, *cw;
    __nv_bfloat16 *ahi, *alo, *wthi, *wtlo;
    double *sumd, *sqsd;
    int *cnt, *cursor, *off, *bsum, *csrc, *gstart;
};

static void run_layer(int K, int N, const float* W, const float* b, const Ptrs& p) {
    int wtot = K * N;
    k_split_wt<<<(wtot + 255) / 256, 256>>>(W, p.wthi, p.wtlo, K, N);

    dim3 grid(N / 128, (NN + 127) / 128);
    k_mma_gemm<<<grid, 256, SMEM_GEMM>>>(p.ahi, p.alo, p.wthi, p.wtlo,
                                         p.h, p.agg, p.dinv, b, NN, K, N);

    int tpnshift = ilog2(N / 4);
    int npb = 128 >> tpnshift;
    k_gather<<<(NN + npb - 1) / npb, 128>>>(p.h, p.csrc, p.cw, p.off, p.agg, N, tpnshift);

    k_zerod<<<(N + 127) / 128, 128>>>(p.sumd, p.sqsd, N);
    dim3 sgrid((N + 255) / 256, 512);
    k_stats<<<sgrid, 256>>>(p.agg, NN, N, p.sumd, p.sqsd);
}

extern "C" void kernel_launch(void* const* d_in, const int* in_sizes, int n_in,
                              void* d_out, int out_size) {
    const float* x     = (const float*)d_in[0];
    const int*   ei    = (const int*)d_in[1];
    const int*   batch = (const int*)d_in[2];
    const float* W1 = (const float*)d_in[3];  const float* b1 = (const float*)d_in[4];
    const float* g1 = (const float*)d_in[5];  const float* be1 = (const float*)d_in[6];
    const float* W2 = (const float*)d_in[7];  const float* b2 = (const float*)d_in[8];
    const float* g2 = (const float*)d_in[9];  const float* be2 = (const float*)d_in[10];
    const float* W3 = (const float*)d_in[11]; const float* b3 = (const float*)d_in[12];
    const float* g3 = (const float*)d_in[13]; const float* be3 = (const float*)d_in[14];
    const float* Wo = (const float*)d_in[15]; const float* bo = (const float*)d_in[16];
    float* out = (float*)d_out;

    int E = in_sizes[1] / 2;
    const int* row = ei;
    const int* col = ei + E;

    Ptrs p;
    cudaGetSymbolAddress((void**)&p.h, g_h);
    cudaGetSymbolAddress((void**)&p.agg, g_agg);
    cudaGetSymbolAddress((void**)&p.ahi, g_ahi);
    cudaGetSymbolAddress((void**)&p.alo, g_alo);
    cudaGetSymbolAddress((void**)&p.wthi, g_wthi);
    cudaGetSymbolAddress((void**)&p.wtlo, g_wtlo);
    cudaGetSymbolAddress((void**)&p.dinv, g_dinv);
    cudaGetSymbolAddress((void**)&p.sumd, g_sumd);
    cudaGetSymbolAddress((void**)&p.sqsd, g_sqsd);
    cudaGetSymbolAddress((void**)&p.mean, g_mean);
    cudaGetSymbolAddress((void**)&p.scale, g_scale);
    cudaGetSymbolAddress((void**)&p.cw, g_cw);
    cudaGetSymbolAddress((void**)&p.cnt, g_cnt);
    cudaGetSymbolAddress((void**)&p.cursor, g_cursor);
    cudaGetSymbolAddress((void**)&p.off, g_off);
    cudaGetSymbolAddress((void**)&p.bsum, g_bsum);
    cudaGetSymbolAddress((void**)&p.csrc, g_csrc);
    cudaGetSymbolAddress((void**)&p.gstart, g_gstart);

    cudaFuncSetAttribute(k_mma_gemm, cudaFuncAttributeMaxDynamicSharedMemorySize,
                         SMEM_GEMM);

    // ---- CSR build + dinv ----
    int nb = (NN + SCAN_B - 1) / SCAN_B;
    k_zeroi<<<(NN + 255) / 256, 256>>>(p.cnt, NN);
    k_count<<<(E + 255) / 256, 256>>>(col, p.cnt, E);
    k_scan1<<<nb, SCAN_B>>>(p.cnt, p.off, p.bsum, NN);
    k_scan2<<<1, 32>>>(p.bsum, nb, p.off);
    if (nb > 1) k_scan3<<<nb - 1, SCAN_B>>>(p.off, p.bsum, NN);
    k_dinv2<<<(NN + 255) / 256, 256>>>(p.cnt, p.dinv, NN);
    k_zeroi<<<(NN + 255) / 256, 256>>>(p.cursor, NN);
    k_place<<<(E + 255) / 256, 256>>>(row, col, p.dinv, p.off, p.cursor, p.csrc, p.cw, E);
    k_bounds<<<(NN + 255) / 256, 256>>>(batch, p.gstart, NN);

    // ---- layer 1 ----
    k_split_plain<<<(NN * 128 + 255) / 256, 256>>>(x, p.ahi, p.alo, NN * 128);
    run_layer(128, 512, W1, b1, p);

    // ---- layer 2 ----
    k_bnparam<<<(512 + 127) / 128, 128>>>(p.sumd, p.sqsd, g1, p.mean, p.scale, 512);
    k_split_bn<<<(NN * 512 + 255) / 256, 256>>>(p.agg, p.ahi, p.alo, p.mean, p.scale,
                                                be1, NN * 512, 511);
    run_layer(512, 256, W2, b2, p);

    // ---- layer 3 ----
    k_bnparam<<<(256 + 127) / 128, 128>>>(p.sumd, p.sqsd, g2, p.mean, p.scale, 256);
    k_split_bn<<<(NN * 256 + 255) / 256, 256>>>(p.agg, p.ahi, p.alo, p.mean, p.scale,
                                                be2, NN * 256, 255);
    run_layer(256, 128, W3, b3, p);

    // ---- final BN + pool + head ----
    k_bnparam<<<1, 128>>>(p.sumd, p.sqsd, g3, p.mean, p.scale, 128);
    k_pool_head<<<NG, 128>>>(p.agg, p.gstart, p.mean, p.scale, be3, Wo, bo, out);
}

// round 8
// speedup vs baseline: 1.1058x; 1.1058x over previous
#include <cuda_runtime.h>
#include <cstdint>

#define NN 50000
#define NG 64
#define MAXE 800000
#define MAXH 512
#define BN_EPS 1e-5f
#define SCAN_B 1024
#define NSTR 250

// ================= scratch (device globals) ===================================
__device__ __align__(16) float g_h[(size_t)NN * MAXH];     // GEMM output
__device__ __align__(16) float g_agg[(size_t)NN * MAXH];   // conv output (raw)
__device__ __align__(16) float g_act[(size_t)NN * MAXH];   // BN+ReLU activations
__device__ float g_dinv[NN];
__device__ int   g_cnt[NN];
__device__ int   g_cursor[NN];
__device__ int   g_off[NN + 1];
__device__ int   g_bsum[64];
__device__ int   g_csrc[MAXE];
__device__ float g_cw[MAXE];
__device__ float g_psum[NSTR * MAXH];
__device__ float g_psqs[NSTR * MAXH];
__device__ __align__(16) float g_mean[MAXH];
__device__ __align__(16) float g_scale[MAXH];
__device__ int   g_gstart[NG + 1];

// ================= CSR build ===================================================
__global__ void k_zeroi(int* p, int n) {
    int i = blockIdx.x * blockDim.x + threadIdx.x;
    if (i < n) p[i] = 0;
}
__global__ void k_count(const int* __restrict__ col, int* cnt, int E) {
    int i = blockIdx.x * blockDim.x + threadIdx.x;
    if (i < E) atomicAdd(&cnt[col[i]], 1);
}
__global__ void k_scan1(const int* __restrict__ cnt, int* off, int* bsum, int n) {
    __shared__ int sh[SCAN_B];
    int i = blockIdx.x * SCAN_B + threadIdx.x;
    sh[threadIdx.x] = (i < n) ? cnt[i] : 0;
    __syncthreads();
#pragma unroll
    for (int d = 1; d < SCAN_B; d <<= 1) {
        int t = (threadIdx.x >= d) ? sh[threadIdx.x - d] : 0;
        __syncthreads();
        sh[threadIdx.x] += t;
        __syncthreads();
    }
    if (i < n) off[i + 1] = sh[threadIdx.x];
    if (threadIdx.x == SCAN_B - 1) bsum[blockIdx.x] = sh[SCAN_B - 1];
}
__global__ void k_scan2(int* bsum, int nb, int* off) {
    if (threadIdx.x == 0) {
        off[0] = 0;
        int s = 0;
        for (int b = 0; b < nb; b++) { s += bsum[b]; bsum[b] = s; }
    }
}
__global__ void k_scan3(int* off, const int* __restrict__ bsum, int n) {
    int b = blockIdx.x + 1;
    int i = b * SCAN_B + threadIdx.x;
    if (i < n) off[i + 1] += bsum[b - 1];
}
__global__ void k_dinv2(const int* __restrict__ cnt, float* dinv, int n) {
    int i = blockIdx.x * blockDim.x + threadIdx.x;
    if (i < n) dinv[i] = rsqrtf((float)(cnt[i] + 1));
}
__global__ void k_place(const int* __restrict__ row, const int* __restrict__ col,
                        const float* __restrict__ dinv, const int* __restrict__ off,
                        int* cursor, int* csrc, float* cw, int E) {
    int e = blockIdx.x * blockDim.x + threadIdx.x;
    if (e >= E) return;
    int d = col[e], r = row[e];
    int pos = off[d] + atomicAdd(&cursor[d], 1);
    csrc[pos] = r;
    cw[pos] = dinv[r] * dinv[d];
}

// ================= cp.async pipelined SGEMM ====================================
// C[M,N] = A[M,K] @ B[K,N].  3-stage cp.async pipeline.
// A stored [m][k] (128 x 16 fp32, 64B rows), B stored [k][n] (16 x 128 fp32).
// Epilogue: H = C ; AGG = C*dinv[row]^2 + bias[col]
#define TBK 16
#define A_ST 8192
#define B_ST 8192
#define STAGE_B (A_ST + B_ST)
#define SMEM_GEMM (3 * STAGE_B)

__device__ __forceinline__ uint32_t smem_u32(const void* p) {
    uint32_t a;
    asm("{ .reg .u64 t; cvta.to.shared.u64 t, %1; cvt.u32.u64 %0, t; }"
        : "=r"(a) : "l"(p));
    return a;
}
__device__ __forceinline__ void cpa16(uint32_t dst, const void* src, int bytes) {
    asm volatile("cp.async.cg.shared.global [%0], [%1], 16, %2;"
                 :: "r"(dst), "l"(src), "r"(bytes) : "memory");
}
#define CP_COMMIT() asm volatile("cp.async.commit_group;" ::: "memory")
#define CP_WAIT1()  asm volatile("cp.async.wait_group 1;" ::: "memory")

__device__ __forceinline__ void stage_load(uint32_t sb, int stage,
                                           const float* __restrict__ A,
                                           const float* __restrict__ B,
                                           int rowBase, int colBase,
                                           int M, int K, int N, int k0, int tid) {
    uint32_t aB = sb + stage * STAGE_B;
    uint32_t bB = aB + A_ST;
    // A: 128 rows x 16 floats (64B) = 512 x 16B chunks
#pragma unroll
    for (int s = 0; s < 2; s++) {
        int q = s * 256 + tid;
        int r = q >> 2;
        int cc = (q & 3) << 2;
        int grow = rowBase + r;
        cpa16(aB + r * 64 + cc * 4, A + (size_t)grow * K + k0 + cc,
              (grow < M) ? 16 : 0);
    }
    // B: 16 rows x 128 floats (512B) = 512 x 16B chunks
#pragma unroll
    for (int s = 0; s < 2; s++) {
        int q = s * 256 + tid;
        int r = q >> 5;
        int cc = (q & 31) << 2;
        cpa16(bB + r * 512 + cc * 4, B + (size_t)(k0 + r) * N + colBase + cc, 16);
    }
}

__global__ __launch_bounds__(256, 2)
void k_gemm_ca(const float* __restrict__ A, const float* __restrict__ B,
               float* __restrict__ Hout, float* __restrict__ AGG,
               const float* __restrict__ dinv, const float* __restrict__ bias,
               int M, int K, int N) {
    extern __shared__ char sm[];
    const uint32_t sb = smem_u32(sm);
    const int tid = threadIdx.x;
    const int rowBase = blockIdx.y * 128;
    const int colBase = blockIdx.x * 128;
    const int tx = tid & 15;
    const int ty = tid >> 4;

    float acc[8][8] = {};
    const int nk = K / TBK;

    // preload stages 0,1
    stage_load(sb, 0, A, B, rowBase, colBase, M, K, N, 0, tid);
    CP_COMMIT();
    stage_load(sb, 1, A, B, rowBase, colBase, M, K, N, TBK, tid);
    CP_COMMIT();

    for (int kt = 0; kt < nk; kt++) {
        CP_WAIT1();
        __syncthreads();

        // prefetch kt+2 (empty commit keeps group accounting exact)
        if (kt + 2 < nk)
            stage_load(sb, (kt + 2) % 3, A, B, rowBase, colBase, M, K, N,
                       (kt + 2) * TBK, tid);
        CP_COMMIT();

        uint32_t aB = sb + (kt % 3) * STAGE_B;
        uint32_t bB = aB + A_ST;

#pragma unroll
        for (int kq = 0; kq < 4; kq++) {
            float4 a4[8];
#pragma unroll
            for (int i = 0; i < 8; i++) {
                int r = (i < 4) ? (ty * 4 + i) : (64 + ty * 4 + i - 4);
                a4[i] = *(const float4*)(sm + (aB - sb) + r * 64 + kq * 16);
            }
#pragma unroll
            for (int kk = 0; kk < 4; kk++) {
                int k = kq * 4 + kk;
                float b[8];
                *(float4*)&b[0] = *(const float4*)(sm + (bB - sb) + k * 512 + tx * 16);
                *(float4*)&b[4] = *(const float4*)(sm + (bB - sb) + k * 512 + 256 + tx * 16);
                float av[8] = {
                    kk == 0 ? a4[0].x : kk == 1 ? a4[0].y : kk == 2 ? a4[0].z : a4[0].w,
                    kk == 0 ? a4[1].x : kk == 1 ? a4[1].y : kk == 2 ? a4[1].z : a4[1].w,
                    kk == 0 ? a4[2].x : kk == 1 ? a4[2].y : kk == 2 ? a4[2].z : a4[2].w,
                    kk == 0 ? a4[3].x : kk == 1 ? a4[3].y : kk == 2 ? a4[3].z : a4[3].w,
                    kk == 0 ? a4[4].x : kk == 1 ? a4[4].y : kk == 2 ? a4[4].z : a4[4].w,
                    kk == 0 ? a4[5].x : kk == 1 ? a4[5].y : kk == 2 ? a4[5].z : a4[5].w,
                    kk == 0 ? a4[6].x : kk == 1 ? a4[6].y : kk == 2 ? a4[6].z : a4[6].w,
                    kk == 0 ? a4[7].x : kk == 1 ? a4[7].y : kk == 2 ? a4[7].z : a4[7].w};
#pragma unroll
                for (int i = 0; i < 8; i++)
#pragma unroll
                    for (int j = 0; j < 8; j++)
                        acc[i][j] += av[i] * b[j];
            }
        }
        __syncthreads();
    }

    // epilogue
    float4 bl0 = *(const float4*)&bias[colBase + tx * 4];
    float4 bl1 = *(const float4*)&bias[colBase + tx * 4 + 64];
    float blo[8] = {bl0.x, bl0.y, bl0.z, bl0.w, bl1.x, bl1.y, bl1.z, bl1.w};

#pragma unroll
    for (int i = 0; i < 8; i++) {
        int r = (i < 4) ? (ty * 4 + i) : (64 + ty * 4 + i - 4);
        int gr = rowBase + r;
        if (gr >= M) continue;
        float di = dinv[gr];
        float d2 = di * di;
        size_t base = (size_t)gr * N;
#pragma unroll
        for (int jj = 0; jj < 2; jj++) {
            int c = colBase + tx * 4 + jj * 64;
            float4 hv = make_float4(acc[i][jj * 4 + 0], acc[i][jj * 4 + 1],
                                    acc[i][jj * 4 + 2], acc[i][jj * 4 + 3]);
            *(float4*)&Hout[base + c] = hv;
            float4 av = make_float4(hv.x * d2 + blo[jj * 4 + 0],
                                    hv.y * d2 + blo[jj * 4 + 1],
                                    hv.z * d2 + blo[jj * 4 + 2],
                                    hv.w * d2 + blo[jj * 4 + 3]);
            *(float4*)&AGG[base + c] = av;
        }
    }
}

// ================= CSR gather ===================================================
__global__ void k_gather(const float* __restrict__ h, const int* __restrict__ csrc,
                         const float* __restrict__ cw, const int* __restrict__ off,
                         float* __restrict__ agg, int H, int tpnshift) {
    int tpn = 1 << tpnshift;
    int local = threadIdx.x >> tpnshift;
    int node = blockIdx.x * (blockDim.x >> tpnshift) + local;
    if (node >= NN) return;
    int c = (threadIdx.x & (tpn - 1)) << 2;
    int s = __ldg(&off[node]);
    int e = __ldg(&off[node + 1]);
    float ax = 0.f, ay = 0.f, az = 0.f, aw = 0.f;
    for (int i = s; i < e; i++) {
        int src = __ldg(&csrc[i]);
        float w = __ldg(&cw[i]);
        float4 v = __ldg((const float4*)(h + (size_t)src * H + c));
        ax += v.x * w; ay += v.y * w; az += v.z * w; aw += v.w * w;
    }
    float4 cur = *(float4*)&agg[(size_t)node * H + c];
    cur.x += ax; cur.y += ay; cur.z += az; cur.w += aw;
    *(float4*)&agg[(size_t)node * H + c] = cur;
}

// ================= BN stats: stripe partials (fp32) + fp64 combine ==============
__global__ void k_stats_part(const float* __restrict__ x, int H,
                             float* __restrict__ psum, float* __restrict__ psqs) {
    int c = blockIdx.x * blockDim.x + threadIdx.x;
    int st = blockIdx.y;
    if (c >= H) return;
    float s = 0.f, q = 0.f;
    for (int r = st; r < NN; r += NSTR) {
        float v = x[(size_t)r * H + c];
        s += v;
        q += v * v;
    }
    psum[st * H + c] = s;
    psqs[st * H + c] = q;
}
__global__ void k_bnparam(const float* __restrict__ psum, const float* __restrict__ psqs,
                          const float* __restrict__ g, float* __restrict__ mean,
                          float* __restrict__ scale, int H) {
    int c = blockIdx.x * blockDim.x + threadIdx.x;
    if (c >= H) return;
    double s = 0.0, q = 0.0;
    for (int st = 0; st < NSTR; st++) {
        s += (double)psum[st * H + c];
        q += (double)psqs[st * H + c];
    }
    const double invN = 1.0 / (double)NN;
    double m = s * invN;
    double var = q * invN - m * m;
    mean[c] = (float)m;
    scale[c] = g[c] * (float)rsqrt(var + (double)BN_EPS);
}

// ================= BN + ReLU materialize ========================================
__global__ void k_bnact(const float* __restrict__ agg, float* __restrict__ act,
                        const float* __restrict__ mean, const float* __restrict__ scale,
                        const float* __restrict__ be, int total4, int hmask4) {
    int i = blockIdx.x * blockDim.x + threadIdx.x;
    if (i >= total4) return;
    int c = (i & hmask4) << 2;
    float4 v = *(const float4*)&agg[(size_t)i * 4];
    float4 mn = *(const float4*)&mean[c];
    float4 sc = *(const float4*)&scale[c];
    float4 bb = *(const float4*)&be[c];
    float4 o;
    o.x = fmaxf((v.x - mn.x) * sc.x + bb.x, 0.f);
    o.y = fmaxf((v.y - mn.y) * sc.y + bb.y, 0.f);
    o.z = fmaxf((v.z - mn.z) * sc.z + bb.z, 0.f);
    o.w = fmaxf((v.w - mn.w) * sc.w + bb.w, 0.f);
    *(float4*)&act[(size_t)i * 4] = o;
}

// ================= graph boundaries + pool head =================================
__global__ void k_bounds(const int* __restrict__ batch, int* gstart, int n) {
    int i = blockIdx.x * blockDim.x + threadIdx.x;
    if (i >= n) return;
    int bi = batch[i];
    int bp = (i == 0) ? -1 : batch[i - 1];
    for (int g = bp + 1; g <= bi; g++) gstart[g] = i;
    if (i == n - 1)
        for (int g = bi + 1; g <= NG; g++) gstart[g] = n;
}
__global__ void k_pool_head(const float* __restrict__ agg, const int* __restrict__ gstart,
                            const float* __restrict__ mean, const float* __restrict__ scale,
                            const float* __restrict__ be, const float* __restrict__ Wo,
                            const float* __restrict__ bo, float* __restrict__ out) {
    __shared__ float pooled[128];
    int g = blockIdx.x;
    int c = threadIdx.x;
    int s = gstart[g], e = gstart[g + 1];
    float mn = mean[c], sc = scale[c], bb = be[c];
    float acc = 0.f;
    for (int n = s; n < e; n++)
        acc += fmaxf((agg[(size_t)n * 128 + c] - mn) * sc + bb, 0.f);
    float inv = 1.0f / (float)max(e - s, 1);
    pooled[c] = acc * inv;
    __syncthreads();
    if (c < 10) {
        float o = bo[c];
#pragma unroll 8
        for (int k = 0; k < 128; k++)
            o += pooled[k] * Wo[k * 10 + c];
        out[g * 10 + c] = o;
    }
}

// ================= host orchestration ===========================================
static inline int ilog2(int v) { int s = 0; while ((1 << s) < v) s++; return s; }

struct Ptrs {
    float *h, *agg, *act, *dinv, *mean, *scale, *cw, *psum, *psqs;
    int *cnt, *cursor, *off, *bsum, *csrc, *gstart;
};

static void run_layer(const float* in, int K, int N, const float* W, const float* b,
                      const Ptrs& p) {
    dim3 grid(N / 128, (NN + 127) / 128);
    k_gemm_ca<<<grid, 256, SMEM_GEMM>>>(in, W, p.h, p.agg, p.dinv, b, NN, K, N);

    int tpnshift = ilog2(N / 4);
    int npb = 128 >> tpnshift;
    k_gather<<<(NN + npb - 1) / npb, 128>>>(p.h, p.csrc, p.cw, p.off, p.agg, N, tpnshift);

    dim3 sgrid((N + 127) / 128, NSTR);
    k_stats_part<<<sgrid, 128>>>(p.agg, N, p.psum, p.psqs);
}

extern "C" void kernel_launch(void* const* d_in, const int* in_sizes, int n_in,
                              void* d_out, int out_size) {
    const float* x     = (const float*)d_in[0];
    const int*   ei    = (const int*)d_in[1];
    const int*   batch = (const int*)d_in[2];
    const float* W1 = (const float*)d_in[3];  const float* b1 = (const float*)d_in[4];
    const float* g1 = (const float*)d_in[5];  const float* be1 = (const float*)d_in[6];
    const float* W2 = (const float*)d_in[7];  const float* b2 = (const float*)d_in[8];
    const float* g2 = (const float*)d_in[9];  const float* be2 = (const float*)d_in[10];
    const float* W3 = (const float*)d_in[11]; const float* b3 = (const float*)d_in[12];
    const float* g3 = (const float*)d_in[13]; const float* be3 = (const float*)d_in[14];
    const float* Wo = (const float*)d_in[15]; const float* bo = (const float*)d_in[16];
    float* out = (float*)d_out;

    int E = in_sizes[1] / 2;
    const int* row = ei;
    const int* col = ei + E;

    Ptrs p;
    cudaGetSymbolAddress((void**)&p.h, g_h);
    cudaGetSymbolAddress((void**)&p.agg, g_agg);
    cudaGetSymbolAddress((void**)&p.act, g_act);
    cudaGetSymbolAddress((void**)&p.dinv, g_dinv);
    cudaGetSymbolAddress((void**)&p.mean, g_mean);
    cudaGetSymbolAddress((void**)&p.scale, g_scale);
    cudaGetSymbolAddress((void**)&p.cw, g_cw);
    cudaGetSymbolAddress((void**)&p.psum, g_psum);
    cudaGetSymbolAddress((void**)&p.psqs, g_psqs);
    cudaGetSymbolAddress((void**)&p.cnt, g_cnt);
    cudaGetSymbolAddress((void**)&p.cursor, g_cursor);
    cudaGetSymbolAddress((void**)&p.off, g_off);
    cudaGetSymbolAddress((void**)&p.bsum, g_bsum);
    cudaGetSymbolAddress((void**)&p.csrc, g_csrc);
    cudaGetSymbolAddress((void**)&p.gstart, g_gstart);

    cudaFuncSetAttribute(k_gemm_ca, cudaFuncAttributeMaxDynamicSharedMemorySize,
                         SMEM_GEMM);

    // ---- CSR build + dinv ----
    int nb = (NN + SCAN_B - 1) / SCAN_B;
    k_zeroi<<<(NN + 255) / 256, 256>>>(p.cnt, NN);
    k_count<<<(E + 255) / 256, 256>>>(col, p.cnt, E);
    k_scan1<<<nb, SCAN_B>>>(p.cnt, p.off, p.bsum, NN);
    k_scan2<<<1, 32>>>(p.bsum, nb, p.off);
    if (nb > 1) k_scan3<<<nb - 1, SCAN_B>>>(p.off, p.bsum, NN);
    k_dinv2<<<(NN + 255) / 256, 256>>>(p.cnt, p.dinv, NN);
    k_zeroi<<<(NN + 255) / 256, 256>>>(p.cursor, NN);
    k_place<<<(E + 255) / 256, 256>>>(row, col, p.dinv, p.off, p.cursor, p.csrc, p.cw, E);
    k_bounds<<<(NN + 255) / 256, 256>>>(batch, p.gstart, NN);

    // ---- layer 1 (raw x input) ----
    run_layer(x, 128, 512, W1, b1, p);

    // ---- layer 2 ----
    k_bnparam<<<(512 + 127) / 128, 128>>>(p.psum, p.psqs, g1, p.mean, p.scale, 512);
    k_bnact<<<(NN * 512 / 4 + 255) / 256, 256>>>(p.agg, p.act, p.mean, p.scale, be1,
                                                 NN * 512 / 4, 512 / 4 - 1);
    run_layer(p.act, 512, 256, W2, b2, p);

    // ---- layer 3 ----
    k_bnparam<<<(256 + 127) / 128, 128>>>(p.psum, p.psqs, g2, p.mean, p.scale, 256);
    k_bnact<<<(NN * 256 / 4 + 255) / 256, 256>>>(p.agg, p.act, p.mean, p.scale, be2,
                                                 NN * 256 / 4, 256 / 4 - 1);
    run_layer(p.act, 256, 128, W3, b3, p);

    // ---- final BN + pool + head ----
    k_bnparam<<<1, 128>>>(p.psum, p.psqs, g3, p.mean, p.scale, 128);
    k_pool_head<<<NG, 128>>>(p.agg, p.gstart, p.mean, p.scale, be3, Wo, bo, out);
}

// round 9
// speedup vs baseline: 1.3200x; 1.1937x over previous
#include <cuda_runtime.h>
#include <cstdint>

#define NN 50000
#define NG 64
#define MAXE 800000
#define MAXH 512
#define BN_EPS 1e-5f
#define SCAN_B 1024
#define NSTR 250

// ================= scratch (device globals) ===================================
__device__ __align__(16) float g_h[(size_t)NN * MAXH];     // GEMM "message" output
__device__ __align__(16) float g_agg[(size_t)NN * MAXH];   // conv out (ping)
__device__ __align__(16) float g_act[(size_t)NN * MAXH];   // conv out (pong) / pre-agg x
__device__ float g_dinv[NN];
__device__ int   g_cnt[NN];
__device__ int   g_cursor[NN];
__device__ int   g_off[NN + 1];
__device__ int   g_bsum[64];
__device__ int   g_csrc[MAXE];
__device__ float g_cw[MAXE];
__device__ float g_psum[NSTR * MAXH];
__device__ float g_psqs[NSTR * MAXH];
__device__ __align__(16) float g_mean[MAXH];
__device__ __align__(16) float g_scale[MAXH];
__device__ int   g_gstart[NG + 1];

// ================= CSR build ===================================================
__global__ void k_zeroi(int* p, int n) {
    int i = blockIdx.x * blockDim.x + threadIdx.x;
    if (i < n) p[i] = 0;
}
__global__ void k_count(const int* __restrict__ col, int* cnt, int E) {
    int i = blockIdx.x * blockDim.x + threadIdx.x;
    if (i < E) atomicAdd(&cnt[col[i]], 1);
}
__global__ void k_scan1(const int* __restrict__ cnt, int* off, int* bsum, int n) {
    __shared__ int sh[SCAN_B];
    int i = blockIdx.x * SCAN_B + threadIdx.x;
    sh[threadIdx.x] = (i < n) ? cnt[i] : 0;
    __syncthreads();
#pragma unroll
    for (int d = 1; d < SCAN_B; d <<= 1) {
        int t = (threadIdx.x >= d) ? sh[threadIdx.x - d] : 0;
        __syncthreads();
        sh[threadIdx.x] += t;
        __syncthreads();
    }
    if (i < n) off[i + 1] = sh[threadIdx.x];
    if (threadIdx.x == SCAN_B - 1) bsum[blockIdx.x] = sh[SCAN_B - 1];
}
__global__ void k_scan2(int* bsum, int nb, int* off) {
    if (threadIdx.x == 0) {
        off[0] = 0;
        int s = 0;
        for (int b = 0; b < nb; b++) { s += bsum[b]; bsum[b] = s; }
    }
}
__global__ void k_scan3(int* off, const int* __restrict__ bsum, int n) {
    int b = blockIdx.x + 1;
    int i = b * SCAN_B + threadIdx.x;
    if (i < n) off[i + 1] += bsum[b - 1];
}
__global__ void k_dinv2(const int* __restrict__ cnt, float* dinv, int n) {
    int i = blockIdx.x * blockDim.x + threadIdx.x;
    if (i < n) dinv[i] = rsqrtf((float)(cnt[i] + 1));
}
__global__ void k_place(const int* __restrict__ row, const int* __restrict__ col,
                        const float* __restrict__ dinv, const int* __restrict__ off,
                        int* cursor, int* csrc, float* cw, int E) {
    int e = blockIdx.x * blockDim.x + threadIdx.x;
    if (e >= E) return;
    int d = col[e], r = row[e];
    int pos = off[d] + atomicAdd(&cursor[d], 1);
    csrc[pos] = r;
    cw[pos] = dinv[r] * dinv[d];
}

// ================= SIMT GEMM (double-buffered, BN-in-A-load) ===================
// C = act(A)[M,K] @ B[K,N]; act = BN+ReLU when BN.
// DUAL: H=C, AGG=C*dinv²+bias (post-agg layers).  !DUAL: AGG=C+bias (pre-agg).
#define TBM 128
#define TBN 128
#define TBK 16
#define ASTRIDE 132

template <bool BN, bool DUAL>
__global__ __launch_bounds__(256, 2)
void k_gemm_fused(const float* __restrict__ A, const float* __restrict__ B,
                  float* __restrict__ H, float* __restrict__ AGG,
                  const float* __restrict__ dinv, const float* __restrict__ bias,
                  const float* __restrict__ meanK, const float* __restrict__ scaleK,
                  const float* __restrict__ beK,
                  int M, int K, int N) {
    __shared__ float As[2][TBK][ASTRIDE];
    __shared__ float Bs[2][TBK][TBN];

    const int tid = threadIdx.x;
    const int rowBase = blockIdx.y * TBM;
    const int colBase = blockIdx.x * TBN;

    const int ar = tid >> 2;
    const int ac = (tid & 3) << 2;
    const int br = tid >> 5;
    const int bc = (tid & 31) << 2;
    const int tx = tid & 15;
    const int ty = tid >> 4;

    float acc[8][8] = {};
    const int nk = K / TBK;

    {
        float4 mn, sc, be;
        if (BN) {
            mn = *(const float4*)&meanK[ac];
            sc = *(const float4*)&scaleK[ac];
            be = *(const float4*)&beK[ac];
        }
#pragma unroll
        for (int s = 0; s < 2; s++) {
            int r = ar + s * 64;
            int gr = rowBase + r;
            float4 v = make_float4(0.f, 0.f, 0.f, 0.f);
            if (gr < M) {
                v = *(const float4*)&A[(size_t)gr * K + ac];
                if (BN) {
                    v.x = fmaxf((v.x - mn.x) * sc.x + be.x, 0.f);
                    v.y = fmaxf((v.y - mn.y) * sc.y + be.y, 0.f);
                    v.z = fmaxf((v.z - mn.z) * sc.z + be.z, 0.f);
                    v.w = fmaxf((v.w - mn.w) * sc.w + be.w, 0.f);
                }
            }
            As[0][ac + 0][r] = v.x; As[0][ac + 1][r] = v.y;
            As[0][ac + 2][r] = v.z; As[0][ac + 3][r] = v.w;
        }
#pragma unroll
        for (int s = 0; s < 2; s++) {
            int r = br + s * 8;
            *(float4*)&Bs[0][r][bc] = *(const float4*)&B[(size_t)r * N + colBase + bc];
        }
    }
    __syncthreads();

    for (int kt = 0; kt < nk; kt++) {
        int buf = kt & 1;
        if (kt + 1 < nk) {
            int k0 = (kt + 1) * TBK;
            float4 mn, sc, be;
            if (BN) {
                mn = *(const float4*)&meanK[k0 + ac];
                sc = *(const float4*)&scaleK[k0 + ac];
                be = *(const float4*)&beK[k0 + ac];
            }
#pragma unroll
            for (int s = 0; s < 2; s++) {
                int r = ar + s * 64;
                int gr = rowBase + r;
                float4 v = make_float4(0.f, 0.f, 0.f, 0.f);
                if (gr < M) {
                    v = *(const float4*)&A[(size_t)gr * K + k0 + ac];
                    if (BN) {
                        v.x = fmaxf((v.x - mn.x) * sc.x + be.x, 0.f);
                        v.y = fmaxf((v.y - mn.y) * sc.y + be.y, 0.f);
                        v.z = fmaxf((v.z - mn.z) * sc.z + be.z, 0.f);
                        v.w = fmaxf((v.w - mn.w) * sc.w + be.w, 0.f);
                    }
                }
                As[buf ^ 1][ac + 0][r] = v.x; As[buf ^ 1][ac + 1][r] = v.y;
                As[buf ^ 1][ac + 2][r] = v.z; As[buf ^ 1][ac + 3][r] = v.w;
            }
#pragma unroll
            for (int s = 0; s < 2; s++) {
                int r = br + s * 8;
                *(float4*)&Bs[buf ^ 1][r][bc] =
                    *(const float4*)&B[(size_t)(k0 + r) * N + colBase + bc];
            }
        }

#pragma unroll
        for (int k = 0; k < TBK; k++) {
            float a[8], b[8];
            *(float4*)&a[0] = *(const float4*)&As[buf][k][ty * 4];
            *(float4*)&a[4] = *(const float4*)&As[buf][k][ty * 4 + 64];
            *(float4*)&b[0] = *(const float4*)&Bs[buf][k][tx * 4];
            *(float4*)&b[4] = *(const float4*)&Bs[buf][k][tx * 4 + 64];
#pragma unroll
            for (int i = 0; i < 8; i++)
#pragma unroll
                for (int j = 0; j < 8; j++)
                    acc[i][j] += a[i] * b[j];
        }
        __syncthreads();
    }

    float4 bl0 = *(const float4*)&bias[colBase + tx * 4];
    float4 bl1 = *(const float4*)&bias[colBase + tx * 4 + 64];
    float blo[8] = {bl0.x, bl0.y, bl0.z, bl0.w, bl1.x, bl1.y, bl1.z, bl1.w};

#pragma unroll
    for (int i = 0; i < 8; i++) {
        int r = (i < 4) ? (ty * 4 + i) : (ty * 4 + 64 + i - 4);
        int gr = rowBase + r;
        if (gr >= M) continue;
        float d2 = 0.f;
        if (DUAL) {
            float di = dinv[gr];
            d2 = di * di;
        }
        size_t base = (size_t)gr * N;
#pragma unroll
        for (int jj = 0; jj < 2; jj++) {
            int c = colBase + tx * 4 + jj * 64;
            float4 hv = make_float4(acc[i][jj * 4 + 0], acc[i][jj * 4 + 1],
                                    acc[i][jj * 4 + 2], acc[i][jj * 4 + 3]);
            if (DUAL) {
                *(float4*)&H[base + c] = hv;
                float4 av = make_float4(hv.x * d2 + blo[jj * 4 + 0],
                                        hv.y * d2 + blo[jj * 4 + 1],
                                        hv.z * d2 + blo[jj * 4 + 2],
                                        hv.w * d2 + blo[jj * 4 + 3]);
                *(float4*)&AGG[base + c] = av;
            } else {
                float4 av = make_float4(hv.x + blo[jj * 4 + 0],
                                        hv.y + blo[jj * 4 + 1],
                                        hv.z + blo[jj * 4 + 2],
                                        hv.w + blo[jj * 4 + 3]);
                *(float4*)&AGG[base + c] = av;
            }
        }
    }
}

// ================= CSR gathers ==================================================
// post-agg: agg[n] += sum w*h[src]   (agg pre-initialized by GEMM epilogue)
__global__ void k_gather(const float* __restrict__ h, const int* __restrict__ csrc,
                         const float* __restrict__ cw, const int* __restrict__ off,
                         float* __restrict__ agg, int H, int tpnshift) {
    int tpn = 1 << tpnshift;
    int local = threadIdx.x >> tpnshift;
    int node = blockIdx.x * (blockDim.x >> tpnshift) + local;
    if (node >= NN) return;
    int c = (threadIdx.x & (tpn - 1)) << 2;
    int s = __ldg(&off[node]);
    int e = __ldg(&off[node + 1]);
    float ax = 0.f, ay = 0.f, az = 0.f, aw = 0.f;
    for (int i = s; i < e; i++) {
        int src = __ldg(&csrc[i]);
        float w = __ldg(&cw[i]);
        float4 v = __ldg((const float4*)(h + (size_t)src * H + c));
        ax += v.x * w; ay += v.y * w; az += v.z * w; aw += v.w * w;
    }
    float4 cur = *(float4*)&agg[(size_t)node * H + c];
    cur.x += ax; cur.y += ay; cur.z += az; cur.w += aw;
    *(float4*)&agg[(size_t)node * H + c] = cur;
}

// pre-agg: out[n] = x[n]*dinv[n]^2 + sum w*x[src]   (H = 128)
__global__ void k_gather_pre(const float* __restrict__ x, const int* __restrict__ csrc,
                             const float* __restrict__ cw, const int* __restrict__ off,
                             const float* __restrict__ dinv, float* __restrict__ out) {
    const int H = 128;
    int local = threadIdx.x >> 5;
    int node = blockIdx.x * 4 + local;
    if (node >= NN) return;
    int c = (threadIdx.x & 31) << 2;
    int s = __ldg(&off[node]);
    int e = __ldg(&off[node + 1]);
    float di = __ldg(&dinv[node]);
    float d2 = di * di;
    float4 xv = __ldg((const float4*)(x + (size_t)node * H + c));
    float ax = xv.x * d2, ay = xv.y * d2, az = xv.z * d2, aw = xv.w * d2;
    for (int i = s; i < e; i++) {
        int src = __ldg(&csrc[i]);
        float w = __ldg(&cw[i]);
        float4 v = __ldg((const float4*)(x + (size_t)src * H + c));
        ax += v.x * w; ay += v.y * w; az += v.z * w; aw += v.w * w;
    }
    *(float4*)&out[(size_t)node * H + c] = make_float4(ax, ay, az, aw);
}

// ================= BN stats: stripe partials (fp32) + fp64 combine ==============
__global__ void k_stats_part(const float* __restrict__ x, int H,
                             float* __restrict__ psum, float* __restrict__ psqs) {
    int c = blockIdx.x * blockDim.x + threadIdx.x;
    int st = blockIdx.y;
    if (c >= H) return;
    float s = 0.f, q = 0.f;
    for (int r = st; r < NN; r += NSTR) {
        float v = x[(size_t)r * H + c];
        s += v;
        q += v * v;
    }
    psum[st * H + c] = s;
    psqs[st * H + c] = q;
}
__global__ void k_bnparam(const float* __restrict__ psum, const float* __restrict__ psqs,
                          const float* __restrict__ g, float* __restrict__ mean,
                          float* __restrict__ scale, int H) {
    int c = blockIdx.x * blockDim.x + threadIdx.x;
    if (c >= H) return;
    double s = 0.0, q = 0.0;
    for (int st = 0; st < NSTR; st++) {
        s += (double)psum[st * H + c];
        q += (double)psqs[st * H + c];
    }
    const double invN = 1.0 / (double)NN;
    double m = s * invN;
    double var = q * invN - m * m;
    mean[c] = (float)m;
    scale[c] = g[c] * (float)rsqrt(var + (double)BN_EPS);
}

// ================= graph boundaries + pool head =================================
__global__ void k_bounds(const int* __restrict__ batch, int* gstart, int n) {
    int i = blockIdx.x * blockDim.x + threadIdx.x;
    if (i >= n) return;
    int bi = batch[i];
    int bp = (i == 0) ? -1 : batch[i - 1];
    for (int g = bp + 1; g <= bi; g++) gstart[g] = i;
    if (i == n - 1)
        for (int g = bi + 1; g <= NG; g++) gstart[g] = n;
}
__global__ void k_pool_head(const float* __restrict__ agg, const int* __restrict__ gstart,
                            const float* __restrict__ mean, const float* __restrict__ scale,
                            const float* __restrict__ be, const float* __restrict__ Wo,
                            const float* __restrict__ bo, float* __restrict__ out) {
    __shared__ float pooled[128];
    int g = blockIdx.x;
    int c = threadIdx.x;
    int s = gstart[g], e = gstart[g + 1];
    float mn = mean[c], sc = scale[c], bb = be[c];
    float acc = 0.f;
    for (int n = s; n < e; n++)
        acc += fmaxf((agg[(size_t)n * 128 + c] - mn) * sc + bb, 0.f);
    float inv = 1.0f / (float)max(e - s, 1);
    pooled[c] = acc * inv;
    __syncthreads();
    if (c < 10) {
        float o = bo[c];
#pragma unroll 8
        for (int k = 0; k < 128; k++)
            o += pooled[k] * Wo[k * 10 + c];
        out[g * 10 + c] = o;
    }
}

// ================= host orchestration ===========================================
static inline int ilog2(int v) { int s = 0; while ((1 << s) < v) s++; return s; }

extern "C" void kernel_launch(void* const* d_in, const int* in_sizes, int n_in,
                              void* d_out, int out_size) {
    const float* x     = (const float*)d_in[0];
    const int*   ei    = (const int*)d_in[1];
    const int*   batch = (const int*)d_in[2];
    const float* W1 = (const float*)d_in[3];  const float* b1 = (const float*)d_in[4];
    const float* g1 = (const float*)d_in[5];  const float* be1 = (const float*)d_in[6];
    const float* W2 = (const float*)d_in[7];  const float* b2 = (const float*)d_in[8];
    const float* g2 = (const float*)d_in[9];  const float* be2 = (const float*)d_in[10];
    const float* W3 = (const float*)d_in[11]; const float* b3 = (const float*)d_in[12];
    const float* g3 = (const float*)d_in[13]; const float* be3 = (const float*)d_in[14];
    const float* Wo = (const float*)d_in[15]; const float* bo = (const float*)d_in[16];
    float* out = (float*)d_out;

    int E = in_sizes[1] / 2;
    const int* row = ei;
    const int* col = ei + E;

    float *h, *agg, *act, *dinv, *mean, *scale, *cw, *psum, *psqs;
    int *cnt, *cursor, *off, *bsum, *csrc, *gstart;
    cudaGetSymbolAddress((void**)&h, g_h);
    cudaGetSymbolAddress((void**)&agg, g_agg);
    cudaGetSymbolAddress((void**)&act, g_act);
    cudaGetSymbolAddress((void**)&dinv, g_dinv);
    cudaGetSymbolAddress((void**)&mean, g_mean);
    cudaGetSymbolAddress((void**)&scale, g_scale);
    cudaGetSymbolAddress((void**)&cw, g_cw);
    cudaGetSymbolAddress((void**)&psum, g_psum);
    cudaGetSymbolAddress((void**)&psqs, g_psqs);
    cudaGetSymbolAddress((void**)&cnt, g_cnt);
    cudaGetSymbolAddress((void**)&cursor, g_cursor);
    cudaGetSymbolAddress((void**)&off, g_off);
    cudaGetSymbolAddress((void**)&bsum, g_bsum);
    cudaGetSymbolAddress((void**)&csrc, g_csrc);
    cudaGetSymbolAddress((void**)&gstart, g_gstart);

    // ---- CSR build + dinv ----
    int nb = (NN + SCAN_B - 1) / SCAN_B;
    k_zeroi<<<(NN + 255) / 256, 256>>>(cnt, NN);
    k_count<<<(E + 255) / 256, 256>>>(col, cnt, E);
    k_scan1<<<nb, SCAN_B>>>(cnt, off, bsum, NN);
    k_scan2<<<1, 32>>>(bsum, nb, off);
    if (nb > 1) k_scan3<<<nb - 1, SCAN_B>>>(off, bsum, NN);
    k_dinv2<<<(NN + 255) / 256, 256>>>(cnt, dinv, NN);
    k_zeroi<<<(NN + 255) / 256, 256>>>(cursor, NN);
    k_place<<<(E + 255) / 256, 256>>>(row, col, dinv, off, cursor, csrc, cw, E);
    k_bounds<<<(NN + 255) / 256, 256>>>(batch, gstart, NN);

    const int GY = (NN + TBM - 1) / TBM;

    // ---- layer 1: PRE-aggregate x (width 128), then GEMM -> agg (conv1 out) ----
    k_gather_pre<<<(NN + 3) / 4, 128>>>(x, csrc, cw, off, dinv, act);
    {
        dim3 grid(512 / TBN, GY);
        k_gemm_fused<false, false><<<grid, 256>>>(act, W1, nullptr, agg, nullptr, b1,
                                                  nullptr, nullptr, nullptr,
                                                  NN, 128, 512);
    }
    {
        dim3 sgrid((512 + 127) / 128, NSTR);
        k_stats_part<<<sgrid, 128>>>(agg, 512, psum, psqs);
    }

    // ---- layer 2: BN fused in GEMM A-load; POST-aggregate (width 256) ----
    k_bnparam<<<(512 + 127) / 128, 128>>>(psum, psqs, g1, mean, scale, 512);
    {
        dim3 grid(256 / TBN, GY);
        k_gemm_fused<true, true><<<grid, 256>>>(agg, W2, h, act, dinv, b2,
                                                mean, scale, be1, NN, 512, 256);
    }
    {
        int tpnshift = ilog2(256 / 4);      // 6 -> 2 nodes/block
        k_gather<<<(NN + 1) / 2, 128>>>(h, csrc, cw, off, act, 256, tpnshift);
        dim3 sgrid((256 + 127) / 128, NSTR);
        k_stats_part<<<sgrid, 128>>>(act, 256, psum, psqs);
    }

    // ---- layer 3: BN fused; POST-aggregate (width 128) ----
    k_bnparam<<<(256 + 127) / 128, 128>>>(psum, psqs, g2, mean, scale, 256);
    {
        dim3 grid(128 / TBN, GY);
        k_gemm_fused<true, true><<<grid, 256>>>(act, W3, h, agg, dinv, b3,
                                                mean, scale, be2, NN, 256, 128);
    }
    {
        int tpnshift = ilog2(128 / 4);      // 5 -> 4 nodes/block
        k_gather<<<(NN + 3) / 4, 128>>>(h, csrc, cw, off, agg, 128, tpnshift);
        dim3 sgrid(1, NSTR);
        k_stats_part<<<sgrid, 128>>>(agg, 128, psum, psqs);
    }

    // ---- final BN + pool + head ----
    k_bnparam<<<1, 128>>>(psum, psqs, g3, mean, scale, 128);
    k_pool_head<<<NG, 128>>>(agg, gstart, mean, scale, be3, Wo, bo, out);
}

// round 10
// speedup vs baseline: 1.3844x; 1.0487x over previous
#include <cuda_runtime.h>
#include <cstdint>

#define NN 50000
#define NG 64
#define MAXE 800000
#define MAXH 512
#define BN_EPS 1e-5f
#define SCAN_B 1024
#define NSTR 250

// ================= scratch (device globals) ===================================
__device__ __align__(16) float g_h[(size_t)NN * MAXH];     // GEMM "message" output
__device__ __align__(16) float g_agg[(size_t)NN * MAXH];   // conv out (ping)
__device__ __align__(16) float g_act[(size_t)NN * MAXH];   // conv out (pong) / pre-agg x
__device__ float g_dinv[NN];
__device__ int   g_cnt[NN];
__device__ int   g_cursor[NN];
__device__ int   g_off[NN + 1];
__device__ int   g_bsum[64];
__device__ int   g_csrc[MAXE];
__device__ float g_cw[MAXE];
__device__ float g_psum[NSTR * MAXH];
__device__ float g_psqs[NSTR * MAXH];
__device__ __align__(16) float g_mean[MAXH];
__device__ __align__(16) float g_scale[MAXH];
__device__ int   g_gstart[NG + 1];

// ================= CSR build ===================================================
__global__ void k_zeroi(int* p, int n) {
    int i = blockIdx.x * blockDim.x + threadIdx.x;
    if (i < n) p[i] = 0;
}
__global__ void k_count(const int* __restrict__ col, int* cnt, int E) {
    int i = blockIdx.x * blockDim.x + threadIdx.x;
    if (i < E) atomicAdd(&cnt[col[i]], 1);
}
__global__ void k_scan1(const int* __restrict__ cnt, int* off, int* bsum, int n) {
    __shared__ int sh[SCAN_B];
    int i = blockIdx.x * SCAN_B + threadIdx.x;
    sh[threadIdx.x] = (i < n) ? cnt[i] : 0;
    __syncthreads();
#pragma unroll
    for (int d = 1; d < SCAN_B; d <<= 1) {
        int t = (threadIdx.x >= d) ? sh[threadIdx.x - d] : 0;
        __syncthreads();
        sh[threadIdx.x] += t;
        __syncthreads();
    }
    if (i < n) off[i + 1] = sh[threadIdx.x];
    if (threadIdx.x == SCAN_B - 1) bsum[blockIdx.x] = sh[SCAN_B - 1];
}
__global__ void k_scan2(int* bsum, int nb, int* off) {
    if (threadIdx.x == 0) {
        off[0] = 0;
        int s = 0;
        for (int b = 0; b < nb; b++) { s += bsum[b]; bsum[b] = s; }
    }
}
__global__ void k_scan3(int* off, const int* __restrict__ bsum, int n) {
    int b = blockIdx.x + 1;
    int i = b * SCAN_B + threadIdx.x;
    if (i < n) off[i + 1] += bsum[b - 1];
}
__global__ void k_dinv2(const int* __restrict__ cnt, float* dinv, int n) {
    int i = blockIdx.x * blockDim.x + threadIdx.x;
    if (i < n) dinv[i] = rsqrtf((float)(cnt[i] + 1));
}
__global__ void k_place(const int* __restrict__ row, const int* __restrict__ col,
                        const float* __restrict__ dinv, const int* __restrict__ off,
                        int* cursor, int* csrc, float* cw, int E) {
    int e = blockIdx.x * blockDim.x + threadIdx.x;
    if (e >= E) return;
    int d = col[e], r = row[e];
    int pos = off[d] + atomicAdd(&cursor[d], 1);
    csrc[pos] = r;
    cw[pos] = dinv[r] * dinv[d];
}

// ================= SIMT GEMM (double-buffered, BN-in-A-load, FFMA2) ============
// C = act(A)[M,K] @ B[K,N]; act = BN+ReLU when BN.
// DUAL: H=C, AGG=C*dinv²+bias (post-agg layers).  !DUAL: AGG=C+bias (pre-agg).
#define TBM 128
#define TBN 128
#define TBK 16
#define ASTRIDE 132

template <bool BN, bool DUAL>
__global__ __launch_bounds__(256, 2)
void k_gemm_fused(const float* __restrict__ A, const float* __restrict__ B,
                  float* __restrict__ H, float* __restrict__ AGG,
                  const float* __restrict__ dinv, const float* __restrict__ bias,
                  const float* __restrict__ meanK, const float* __restrict__ scaleK,
                  const float* __restrict__ beK,
                  int M, int K, int N) {
    __shared__ float As[2][TBK][ASTRIDE];
    __shared__ float Bs[2][TBK][TBN];

    const int tid = threadIdx.x;
    const int rowBase = blockIdx.y * TBM;
    const int colBase = blockIdx.x * TBN;

    const int ar = tid >> 2;
    const int ac = (tid & 3) << 2;
    const int br = tid >> 5;
    const int bc = (tid & 31) << 2;
    const int tx = tid & 15;
    const int ty = tid >> 4;

    // packed fp32 accumulators: acc2[i][j] = cols (j<2 ? tx*4+j*2 : tx*4+64+(j-2)*2)
    unsigned long long acc2[8][4];
#pragma unroll
    for (int i = 0; i < 8; i++)
#pragma unroll
        for (int j = 0; j < 4; j++) acc2[i][j] = 0ULL;

    const int nk = K / TBK;

    {
        float4 mn, sc, be;
        if (BN) {
            mn = *(const float4*)&meanK[ac];
            sc = *(const float4*)&scaleK[ac];
            be = *(const float4*)&beK[ac];
        }
#pragma unroll
        for (int s = 0; s < 2; s++) {
            int r = ar + s * 64;
            int gr = rowBase + r;
            float4 v = make_float4(0.f, 0.f, 0.f, 0.f);
            if (gr < M) {
                v = *(const float4*)&A[(size_t)gr * K + ac];
                if (BN) {
                    v.x = fmaxf((v.x - mn.x) * sc.x + be.x, 0.f);
                    v.y = fmaxf((v.y - mn.y) * sc.y + be.y, 0.f);
                    v.z = fmaxf((v.z - mn.z) * sc.z + be.z, 0.f);
                    v.w = fmaxf((v.w - mn.w) * sc.w + be.w, 0.f);
                }
            }
            As[0][ac + 0][r] = v.x; As[0][ac + 1][r] = v.y;
            As[0][ac + 2][r] = v.z; As[0][ac + 3][r] = v.w;
        }
#pragma unroll
        for (int s = 0; s < 2; s++) {
            int r = br + s * 8;
            *(float4*)&Bs[0][r][bc] = *(const float4*)&B[(size_t)r * N + colBase + bc];
        }
    }
    __syncthreads();

    for (int kt = 0; kt < nk; kt++) {
        int buf = kt & 1;
        if (kt + 1 < nk) {
            int k0 = (kt + 1) * TBK;
            float4 mn, sc, be;
            if (BN) {
                mn = *(const float4*)&meanK[k0 + ac];
                sc = *(const float4*)&scaleK[k0 + ac];
                be = *(const float4*)&beK[k0 + ac];
            }
#pragma unroll
            for (int s = 0; s < 2; s++) {
                int r = ar + s * 64;
                int gr = rowBase + r;
                float4 v = make_float4(0.f, 0.f, 0.f, 0.f);
                if (gr < M) {
                    v = *(const float4*)&A[(size_t)gr * K + k0 + ac];
                    if (BN) {
                        v.x = fmaxf((v.x - mn.x) * sc.x + be.x, 0.f);
                        v.y = fmaxf((v.y - mn.y) * sc.y + be.y, 0.f);
                        v.z = fmaxf((v.z - mn.z) * sc.z + be.z, 0.f);
                        v.w = fmaxf((v.w - mn.w) * sc.w + be.w, 0.f);
                    }
                }
                As[buf ^ 1][ac + 0][r] = v.x; As[buf ^ 1][ac + 1][r] = v.y;
                As[buf ^ 1][ac + 2][r] = v.z; As[buf ^ 1][ac + 3][r] = v.w;
            }
#pragma unroll
            for (int s = 0; s < 2; s++) {
                int r = br + s * 8;
                *(float4*)&Bs[buf ^ 1][r][bc] =
                    *(const float4*)&B[(size_t)(k0 + r) * N + colBase + bc];
            }
        }

#pragma unroll
        for (int k = 0; k < TBK; k++) {
            float a[8], b[8];
            *(float4*)&a[0] = *(const float4*)&As[buf][k][ty * 4];
            *(float4*)&a[4] = *(const float4*)&As[buf][k][ty * 4 + 64];
            *(float4*)&b[0] = *(const float4*)&Bs[buf][k][tx * 4];
            *(float4*)&b[4] = *(const float4*)&Bs[buf][k][tx * 4 + 64];
            unsigned long long bp[4];
#pragma unroll
            for (int j = 0; j < 4; j++)
                asm("mov.b64 %0, {%1, %2};"
                    : "=l"(bp[j]) : "f"(b[j * 2]), "f"(b[j * 2 + 1]));
#pragma unroll
            for (int i = 0; i < 8; i++) {
                unsigned long long ap;
                asm("mov.b64 %0, {%1, %1};" : "=l"(ap) : "f"(a[i]));
#pragma unroll
                for (int j = 0; j < 4; j++)
                    asm("fma.rn.f32x2 %0, %1, %2, %0;"
                        : "+l"(acc2[i][j]) : "l"(ap), "l"(bp[j]));
            }
        }
        __syncthreads();
    }

    float4 bl0 = *(const float4*)&bias[colBase + tx * 4];
    float4 bl1 = *(const float4*)&bias[colBase + tx * 4 + 64];
    float blo[8] = {bl0.x, bl0.y, bl0.z, bl0.w, bl1.x, bl1.y, bl1.z, bl1.w};

#pragma unroll
    for (int i = 0; i < 8; i++) {
        int r = (i < 4) ? (ty * 4 + i) : (ty * 4 + 64 + i - 4);
        int gr = rowBase + r;
        if (gr >= M) continue;
        float d2 = 0.f;
        if (DUAL) {
            float di = dinv[gr];
            d2 = di * di;
        }
        size_t base = (size_t)gr * N;
#pragma unroll
        for (int jj = 0; jj < 2; jj++) {
            int c = colBase + tx * 4 + jj * 64;
            float c0, c1, c2, c3;
            asm("mov.b64 {%0, %1}, %2;" : "=f"(c0), "=f"(c1) : "l"(acc2[i][jj * 2 + 0]));
            asm("mov.b64 {%0, %1}, %2;" : "=f"(c2), "=f"(c3) : "l"(acc2[i][jj * 2 + 1]));
            float4 hv = make_float4(c0, c1, c2, c3);
            if (DUAL) {
                *(float4*)&H[base + c] = hv;
                float4 av = make_float4(hv.x * d2 + blo[jj * 4 + 0],
                                        hv.y * d2 + blo[jj * 4 + 1],
                                        hv.z * d2 + blo[jj * 4 + 2],
                                        hv.w * d2 + blo[jj * 4 + 3]);
                *(float4*)&AGG[base + c] = av;
            } else {
                float4 av = make_float4(hv.x + blo[jj * 4 + 0],
                                        hv.y + blo[jj * 4 + 1],
                                        hv.z + blo[jj * 4 + 2],
                                        hv.w + blo[jj * 4 + 3]);
                *(float4*)&AGG[base + c] = av;
            }
        }
    }
}

// ================= CSR gathers ==================================================
// post-agg: agg[n] += sum w*h[src]   (agg pre-initialized by GEMM epilogue)
__global__ void k_gather(const float* __restrict__ h, const int* __restrict__ csrc,
                         const float* __restrict__ cw, const int* __restrict__ off,
                         float* __restrict__ agg, int H, int tpnshift) {
    int tpn = 1 << tpnshift;
    int local = threadIdx.x >> tpnshift;
    int node = blockIdx.x * (blockDim.x >> tpnshift) + local;
    if (node >= NN) return;
    int c = (threadIdx.x & (tpn - 1)) << 2;
    int s = __ldg(&off[node]);
    int e = __ldg(&off[node + 1]);
    float ax = 0.f, ay = 0.f, az = 0.f, aw = 0.f;
    for (int i = s; i < e; i++) {
        int src = __ldg(&csrc[i]);
        float w = __ldg(&cw[i]);
        float4 v = __ldg((const float4*)(h + (size_t)src * H + c));
        ax += v.x * w; ay += v.y * w; az += v.z * w; aw += v.w * w;
    }
    float4 cur = *(float4*)&agg[(size_t)node * H + c];
    cur.x += ax; cur.y += ay; cur.z += az; cur.w += aw;
    *(float4*)&agg[(size_t)node * H + c] = cur;
}

// pre-agg: out[n] = x[n]*dinv[n]^2 + sum w*x[src]   (H = 128)
__global__ void k_gather_pre(const float* __restrict__ x, const int* __restrict__ csrc,
                             const float* __restrict__ cw, const int* __restrict__ off,
                             const float* __restrict__ dinv, float* __restrict__ out) {
    const int H = 128;
    int local = threadIdx.x >> 5;
    int node = blockIdx.x * 4 + local;
    if (node >= NN) return;
    int c = (threadIdx.x & 31) << 2;
    int s = __ldg(&off[node]);
    int e = __ldg(&off[node + 1]);
    float di = __ldg(&dinv[node]);
    float d2 = di * di;
    float4 xv = __ldg((const float4*)(x + (size_t)node * H + c));
    float ax = xv.x * d2, ay = xv.y * d2, az = xv.z * d2, aw = xv.w * d2;
    for (int i = s; i < e; i++) {
        int src = __ldg(&csrc[i]);
        float w = __ldg(&cw[i]);
        float4 v = __ldg((const float4*)(x + (size_t)src * H + c));
        ax += v.x * w; ay += v.y * w; az += v.z * w; aw += v.w * w;
    }
    *(float4*)&out[(size_t)node * H + c] = make_float4(ax, ay, az, aw);
}

// ================= BN stats: stripe partials (fp32) + fp64 combine ==============
__global__ void k_stats_part(const float* __restrict__ x, int H,
                             float* __restrict__ psum, float* __restrict__ psqs) {
    int c = blockIdx.x * blockDim.x + threadIdx.x;
    int st = blockIdx.y;
    if (c >= H) return;
    float s = 0.f, q = 0.f;
    for (int r = st; r < NN; r += NSTR) {
        float v = x[(size_t)r * H + c];
        s += v;
        q += v * v;
    }
    psum[st * H + c] = s;
    psqs[st * H + c] = q;
}
__global__ void k_bnparam(const float* __restrict__ psum, const float* __restrict__ psqs,
                          const float* __restrict__ g, float* __restrict__ mean,
                          float* __restrict__ scale, int H) {
    int c = blockIdx.x * blockDim.x + threadIdx.x;
    if (c >= H) return;
    double s = 0.0, q = 0.0;
    for (int st = 0; st < NSTR; st++) {
        s += (double)psum[st * H + c];
        q += (double)psqs[st * H + c];
    }
    const double invN = 1.0 / (double)NN;
    double m = s * invN;
    double var = q * invN - m * m;
    mean[c] = (float)m;
    scale[c] = g[c] * (float)rsqrt(var + (double)BN_EPS);
}

// ================= graph boundaries + pool head =================================
__global__ void k_bounds(const int* __restrict__ batch, int* gstart, int n) {
    int i = blockIdx.x * blockDim.x + threadIdx.x;
    if (i >= n) return;
    int bi = batch[i];
    int bp = (i == 0) ? -1 : batch[i - 1];
    for (int g = bp + 1; g <= bi; g++) gstart[g] = i;
    if (i == n - 1)
        for (int g = bi + 1; g <= NG; g++) gstart[g] = n;
}
__global__ void k_pool_head(const float* __restrict__ agg, const int* __restrict__ gstart,
                            const float* __restrict__ mean, const float* __restrict__ scale,
                            const float* __restrict__ be, const float* __restrict__ Wo,
                            const float* __restrict__ bo, float* __restrict__ out) {
    __shared__ float pooled[128];
    int g = blockIdx.x;
    int c = threadIdx.x;
    int s = gstart[g], e = gstart[g + 1];
    float mn = mean[c], sc = scale[c], bb = be[c];
    float acc = 0.f;
    for (int n = s; n < e; n++)
        acc += fmaxf((agg[(size_t)n * 128 + c] - mn) * sc + bb, 0.f);
    float inv = 1.0f / (float)max(e - s, 1);
    pooled[c] = acc * inv;
    __syncthreads();
    if (c < 10) {
        float o = bo[c];
#pragma unroll 8
        for (int k = 0; k < 128; k++)
            o += pooled[k] * Wo[k * 10 + c];
        out[g * 10 + c] = o;
    }
}

// ================= host orchestration ===========================================
static inline int ilog2(int v) { int s = 0; while ((1 << s) < v) s++; return s; }

extern "C" void kernel_launch(void* const* d_in, const int* in_sizes, int n_in,
                              void* d_out, int out_size) {
    const float* x     = (const float*)d_in[0];
    const int*   ei    = (const int*)d_in[1];
    const int*   batch = (const int*)d_in[2];
    const float* W1 = (const float*)d_in[3];  const float* b1 = (const float*)d_in[4];
    const float* g1 = (const float*)d_in[5];  const float* be1 = (const float*)d_in[6];
    const float* W2 = (const float*)d_in[7];  const float* b2 = (const float*)d_in[8];
    const float* g2 = (const float*)d_in[9];  const float* be2 = (const float*)d_in[10];
    const float* W3 = (const float*)d_in[11]; const float* b3 = (const float*)d_in[12];
    const float* g3 = (const float*)d_in[13]; const float* be3 = (const float*)d_in[14];
    const float* Wo = (const float*)d_in[15]; const float* bo = (const float*)d_in[16];
    float* out = (float*)d_out;

    int E = in_sizes[1] / 2;
    const int* row = ei;
    const int* col = ei + E;

    float *h, *agg, *act, *dinv, *mean, *scale, *cw, *psum, *psqs;
    int *cnt, *cursor, *off, *bsum, *csrc, *gstart;
    cudaGetSymbolAddress((void**)&h, g_h);
    cudaGetSymbolAddress((void**)&agg, g_agg);
    cudaGetSymbolAddress((void**)&act, g_act);
    cudaGetSymbolAddress((void**)&dinv, g_dinv);
    cudaGetSymbolAddress((void**)&mean, g_mean);
    cudaGetSymbolAddress((void**)&scale, g_scale);
    cudaGetSymbolAddress((void**)&cw, g_cw);
    cudaGetSymbolAddress((void**)&psum, g_psum);
    cudaGetSymbolAddress((void**)&psqs, g_psqs);
    cudaGetSymbolAddress((void**)&cnt, g_cnt);
    cudaGetSymbolAddress((void**)&cursor, g_cursor);
    cudaGetSymbolAddress((void**)&off, g_off);
    cudaGetSymbolAddress((void**)&bsum, g_bsum);
    cudaGetSymbolAddress((void**)&csrc, g_csrc);
    cudaGetSymbolAddress((void**)&gstart, g_gstart);

    // ---- CSR build + dinv ----
    int nb = (NN + SCAN_B - 1) / SCAN_B;
    k_zeroi<<<(NN + 255) / 256, 256>>>(cnt, NN);
    k_count<<<(E + 255) / 256, 256>>>(col, cnt, E);
    k_scan1<<<nb, SCAN_B>>>(cnt, off, bsum, NN);
    k_scan2<<<1, 32>>>(bsum, nb, off);
    if (nb > 1) k_scan3<<<nb - 1, SCAN_B>>>(off, bsum, NN);
    k_dinv2<<<(NN + 255) / 256, 256>>>(cnt, dinv, NN);
    k_zeroi<<<(NN + 255) / 256, 256>>>(cursor, NN);
    k_place<<<(E + 255) / 256, 256>>>(row, col, dinv, off, cursor, csrc, cw, E);
    k_bounds<<<(NN + 255) / 256, 256>>>(batch, gstart, NN);

    const int GY = (NN + TBM - 1) / TBM;

    // ---- layer 1: PRE-aggregate x (width 128), then GEMM -> agg (conv1 out) ----
    k_gather_pre<<<(NN + 3) / 4, 128>>>(x, csrc, cw, off, dinv, act);
    {
        dim3 grid(512 / TBN, GY);
        k_gemm_fused<false, false><<<grid, 256>>>(act, W1, nullptr, agg, nullptr, b1,
                                                  nullptr, nullptr, nullptr,
                                                  NN, 128, 512);
    }
    {
        dim3 sgrid((512 + 127) / 128, NSTR);
        k_stats_part<<<sgrid, 128>>>(agg, 512, psum, psqs);
    }

    // ---- layer 2: BN fused in GEMM A-load; POST-aggregate (width 256) ----
    k_bnparam<<<(512 + 127) / 128, 128>>>(psum, psqs, g1, mean, scale, 512);
    {
        dim3 grid(256 / TBN, GY);
        k_gemm_fused<true, true><<<grid, 256>>>(agg, W2, h, act, dinv, b2,
                                                mean, scale, be1, NN, 512, 256);
    }
    {
        int tpnshift = ilog2(256 / 4);      // 6 -> 2 nodes/block
        k_gather<<<(NN + 1) / 2, 128>>>(h, csrc, cw, off, act, 256, tpnshift);
        dim3 sgrid((256 + 127) / 128, NSTR);
        k_stats_part<<<sgrid, 128>>>(act, 256, psum, psqs);
    }

    // ---- layer 3: BN fused; POST-aggregate (width 128) ----
    k_bnparam<<<(256 + 127) / 128, 128>>>(psum, psqs, g2, mean, scale, 256);
    {
        dim3 grid(128 / TBN, GY);
        k_gemm_fused<true, true><<<grid, 256>>>(act, W3, h, agg, dinv, b3,
                                                mean, scale, be2, NN, 256, 128);
    }
    {
        int tpnshift = ilog2(128 / 4);      // 5 -> 4 nodes/block
        k_gather<<<(NN + 3) / 4, 128>>>(h, csrc, cw, off, agg, 128, tpnshift);
        dim3 sgrid(1, NSTR);
        k_stats_part<<<sgrid, 128>>>(agg, 128, psum, psqs);
    }

    // ---- final BN + pool + head ----
    k_bnparam<<<1, 128>>>(psum, psqs, g3, mean, scale, 128);
    k_pool_head<<<NG, 128>>>(agg, gstart, mean, scale, be3, Wo, bo, out);
}